// round 5
// baseline (speedup 1.0000x reference)
#include <cuda_runtime.h>

// ---------------- scratch (static device globals; no allocation) ----------------
__device__ float g_h1[8388608];   // [32][64][64][64]  conv1+pool out, NHWC
__device__ float g_f[4194304];    // [32][32][32][128] conv2+pool out, NHWC
__device__ float g_w2t[73728];    // conv2 weights transposed: [ic][woff][oc]
__device__ float g_q[2097152];    // [b*4+n][y][x][16]
__device__ float g_k[2097152];
__device__ float g_v[2097152];
__device__ float g_o[2097152];    // row-attn out [b][y][x][64]
__device__ float g_o2[2097152];   // col-attn out [b][y][x][64]
__device__ float g_pooled[4096];  // [32][128]

// ---------------- packed f32x2 helpers ----------------
__device__ __forceinline__ void ffma2(unsigned long long& d, unsigned long long a,
                                      unsigned long long b) {
  asm("fma.rn.f32x2 %0, %1, %2, %0;" : "+l"(d) : "l"(a), "l"(b));
}
__device__ __forceinline__ unsigned long long pk(float lo, float hi) {
  unsigned long long r;
  asm("mov.b64 %0, {%1,%2};" : "=l"(r) : "f"(lo), "f"(hi));
  return r;
}
__device__ __forceinline__ unsigned long long pk2(float v) { return pk(v, v); }
__device__ __forceinline__ float2 upk(unsigned long long v) {
  float2 r;
  asm("mov.b64 {%0,%1}, %2;" : "=f"(r.x), "=f"(r.y) : "l"(v));
  return r;
}

// ---------------- conv2 weight transpose prep ----------------
__global__ void prep_w2_k(const float* __restrict__ w) {
  int i = blockIdx.x * 256 + threadIdx.x;  // i = ((ic*9)+woff)*128 + oc
  if (i < 73728) {
    int oc = i & 127;
    int rest = i >> 7;
    int woff = rest % 9, ic = rest / 9;
    g_w2t[i] = w[(size_t)oc * 576 + ic * 9 + woff];
  }
}

// ---------------- conv1 (3->64) + relu + maxpool2 (FFMA2) --------------------
__global__ __launch_bounds__(256) void conv1_pool_k(const float* __restrict__ x,
                                                    const float* __restrict__ w,
                                                    const float* __restrict__ bias) {
  __shared__ unsigned long long sw2[1728];  // duplicated (w,w) pairs
  __shared__ float sb[64];
  for (int i = threadIdx.x; i < 1728; i += 256) sw2[i] = pk2(w[i]);
  if (threadIdx.x < 64) sb[threadIdx.x] = bias[threadIdx.x];
  __syncthreads();
  int idx = blockIdx.x * 256 + threadIdx.x;  // (b,py,px) pooled pixel
  int px = idx & 63, py = (idx >> 6) & 63, b = idx >> 12;

  unsigned long long inp[3][4][3];  // [c][row][kw]: (in[r][kw], in[r][kw+1])
#pragma unroll
  for (int c = 0; c < 3; c++) {
#pragma unroll
    for (int r = 0; r < 4; r++) {
      int iy = 2 * py - 1 + r;
      bool yok = (iy >= 0 && iy < 128);
      const float* xr = x + ((size_t)(b * 3 + c) * 128 + (yok ? iy : 0)) * 128;
      float rowv[4];
#pragma unroll
      for (int cc = 0; cc < 4; cc++) {
        int ix = 2 * px - 1 + cc;
        rowv[cc] = (yok && ix >= 0 && ix < 128) ? xr[ix] : 0.f;
      }
#pragma unroll
      for (int kw = 0; kw < 3; kw++) inp[c][r][kw] = pk(rowv[kw], rowv[kw + 1]);
    }
  }
  float* outp = &g_h1[(size_t)idx * 64];
  float4 vbuf;
  float* vb = (float*)&vbuf;
  for (int oc = 0; oc < 64; oc++) {
    float bsv = sb[oc];
    unsigned long long a01 = pk2(bsv);
    unsigned long long a23 = pk2(bsv);
    const unsigned long long* wp = &sw2[oc * 27];
#pragma unroll
    for (int c = 0; c < 3; c++)
#pragma unroll
      for (int kh = 0; kh < 3; kh++)
#pragma unroll
        for (int kw = 0; kw < 3; kw++) {
          unsigned long long wv = wp[c * 9 + kh * 3 + kw];
          ffma2(a01, inp[c][kh][kw], wv);
          ffma2(a23, inp[c][kh + 1][kw], wv);
        }
    float2 f01 = upk(a01), f23 = upk(a23);
    float m = fmaxf(fmaxf(f01.x, f01.y), fmaxf(f23.x, f23.y));
    vb[oc & 3] = fmaxf(m, 0.f);
    if ((oc & 3) == 3) ((float4*)outp)[oc >> 2] = vbuf;
  }
}

// ---------------- conv2 (64->128) + relu + maxpool2 (FFMA2 v3) ---------------
// block: 256 threads = 16 pixels (4x4 pooled tile) x 16 oc-groups (8 oc each)
// input tile cached in smem as pre-duplicated (v,v) 64-bit pairs -> no MOVs.
__global__ __launch_bounds__(256) void conv2_pool_k(const float* __restrict__ bias) {
  __shared__ unsigned long long s_in2[100 * 33];  // 10x10 spatial x 32 ch pairs
  int b = blockIdx.x >> 6;
  int tile = blockIdx.x & 63;
  int ty0 = (tile >> 3) * 4;
  int tx0 = (tile & 7) * 4;
  int tid = threadIdx.x;
  int pix = tid & 15;
  int px = pix & 3, py = pix >> 2;
  int oc0 = (tid >> 4) * 8;

  unsigned long long acc2[4][4];  // [ocpair][pos]
#pragma unroll
  for (int pr = 0; pr < 4; pr++) {
    unsigned long long bp = pk(bias[oc0 + 2 * pr], bias[oc0 + 2 * pr + 1]);
#pragma unroll
    for (int p = 0; p < 4; p++) acc2[pr][p] = bp;
  }

  for (int ic0 = 0; ic0 < 64; ic0 += 32) {
    __syncthreads();
    for (int i = tid; i < 100 * 32; i += 256) {
      int c = i & 31;
      int rc = i >> 5;
      int row = rc / 10, col = rc - row * 10;
      int iy = 2 * ty0 - 1 + row;
      int ix = 2 * tx0 - 1 + col;
      float val = 0.f;
      if (iy >= 0 && iy < 64 && ix >= 0 && ix < 64)
        val = g_h1[((size_t)(b * 64 + iy) * 64 + ix) * 64 + ic0 + c];
      s_in2[rc * 33 + c] = pk2(val);
    }
    __syncthreads();
#pragma unroll 2
    for (int ic = 0; ic < 32; ic++) {
      unsigned long long ivp[4][4];
#pragma unroll
      for (int r = 0; r < 4; r++)
#pragma unroll
        for (int cc = 0; cc < 4; cc++)
          ivp[r][cc] = s_in2[((2 * py + r) * 10 + 2 * px + cc) * 33 + ic];
      const float* wb = &g_w2t[(size_t)(ic0 + ic) * 1152 + oc0];
#pragma unroll
      for (int kh = 0; kh < 3; kh++)
#pragma unroll
        for (int kw = 0; kw < 3; kw++) {
          int woff = kh * 3 + kw;
          ulonglong2 wA = *(const ulonglong2*)(wb + woff * 128);
          ulonglong2 wB = *(const ulonglong2*)(wb + woff * 128 + 4);
#pragma unroll
          for (int p = 0; p < 4; p++) {
            unsigned long long a = ivp[kh + (p >> 1)][kw + (p & 1)];
            ffma2(acc2[0][p], a, wA.x);
            ffma2(acc2[1][p], a, wA.y);
            ffma2(acc2[2][p], a, wB.x);
            ffma2(acc2[3][p], a, wB.y);
          }
        }
    }
  }
  int y = ty0 + py, xo = tx0 + px;
  float* outp = &g_f[((size_t)(b * 32 + y) * 32 + xo) * 128 + oc0];
  float res[8];
#pragma unroll
  for (int pr = 0; pr < 4; pr++) {
    float2 f0 = upk(acc2[pr][0]), f1 = upk(acc2[pr][1]);
    float2 f2 = upk(acc2[pr][2]), f3 = upk(acc2[pr][3]);
    res[2 * pr] = fmaxf(fmaxf(fmaxf(f0.x, f1.x), fmaxf(f2.x, f3.x)), 0.f);
    res[2 * pr + 1] = fmaxf(fmaxf(fmaxf(f0.y, f1.y), fmaxf(f2.y, f3.y)), 0.f);
  }
  ((float4*)outp)[0] = make_float4(res[0], res[1], res[2], res[3]);
  ((float4*)outp)[1] = make_float4(res[4], res[5], res[6], res[7]);
}

// ---------------- fused Q/K/V projection (FFMA2, M=128 tile) -----------------
// block 256: tile M=128, N=64; thread: ty(0..31) -> 4 m rows, tx(0..7) -> 8 n (4 pairs)
__global__ __launch_bounds__(256) void qkv_k(const float* __restrict__ qw, const float* __restrict__ qb,
                                             const float* __restrict__ kw, const float* __restrict__ kb,
                                             const float* __restrict__ vw, const float* __restrict__ vb) {
  __shared__ unsigned long long As2[128 * 33];  // [m][kk] duplicated pairs (33.8KB)
  __shared__ float Bs[32 * 68];                 // [kk][n] n-contiguous (8.7KB)
  int which = blockIdx.y;
  const float* W = which == 0 ? qw : (which == 1 ? kw : vw);
  const float* bi = which == 0 ? qb : (which == 1 ? kb : vb);
  float* dst = which == 0 ? g_q : (which == 1 ? g_k : g_v);
  float scale = which == 0 ? 0.25f : 1.0f;
  int m0 = blockIdx.x * 128;
  int tid = threadIdx.x;
  int tx = tid & 7, ty = tid >> 3;
  unsigned long long acc2[4][4] = {};
  for (int k0 = 0; k0 < 128; k0 += 32) {
    __syncthreads();
#pragma unroll
    for (int t = 0; t < 4; t++) {
      int i = tid + t * 256;       // 1024 float4 groups: r = i>>3, f4 = i&7
      int r = i >> 3, f4 = i & 7;
      float4 v = *(const float4*)&g_f[(size_t)(m0 + r) * 128 + k0 + f4 * 4];
      unsigned long long* d = &As2[r * 33 + f4 * 4];
      d[0] = pk2(v.x); d[1] = pk2(v.y); d[2] = pk2(v.z); d[3] = pk2(v.w);
    }
#pragma unroll
    for (int t = 0; t < 8; t++) {
      int i = tid + t * 256;
      int kk = i & 31, n = i >> 5;
      Bs[kk * 68 + n] = W[(size_t)n * 128 + k0 + kk];
    }
    __syncthreads();
#pragma unroll
    for (int kk = 0; kk < 32; kk++) {
      ulonglong2 b0 = *(const ulonglong2*)&Bs[kk * 68 + tx * 8];      // pairs n0n1,n2n3
      ulonglong2 b1 = *(const ulonglong2*)&Bs[kk * 68 + tx * 8 + 4];  // pairs n4n5,n6n7
      unsigned long long a[4];
#pragma unroll
      for (int i = 0; i < 4; i++) a[i] = As2[(ty * 4 + i) * 33 + kk];
#pragma unroll
      for (int i = 0; i < 4; i++) {
        ffma2(acc2[i][0], a[i], b0.x);
        ffma2(acc2[i][1], a[i], b0.y);
        ffma2(acc2[i][2], a[i], b1.x);
        ffma2(acc2[i][3], a[i], b1.y);
      }
    }
  }
  int n_head = tx >> 1, d0 = (tx & 1) * 8;
  float bv[8];
#pragma unroll
  for (int j = 0; j < 8; j++) bv[j] = bi[tx * 8 + j];
#pragma unroll
  for (int i = 0; i < 4; i++) {
    int m = m0 + ty * 4 + i;
    int bimg = m >> 10, y = (m >> 5) & 31, xx = m & 31;
    size_t base = ((size_t)(bimg * 4 + n_head) * 1024 + y * 32 + xx) * 16 + d0;
    float2 p0 = upk(acc2[i][0]), p1 = upk(acc2[i][1]);
    float2 p2 = upk(acc2[i][2]), p3 = upk(acc2[i][3]);
    *(float4*)&dst[base] = make_float4((p0.x + bv[0]) * scale, (p0.y + bv[1]) * scale,
                                       (p1.x + bv[2]) * scale, (p1.y + bv[3]) * scale);
    *(float4*)&dst[base + 4] = make_float4((p2.x + bv[4]) * scale, (p2.y + bv[5]) * scale,
                                           (p3.x + bv[6]) * scale, (p3.y + bv[7]) * scale);
  }
}

// ---------------- axial attention: merged row+col, float4 smem reads ----------
__global__ __launch_bounds__(256) void attn_k(const float* __restrict__ rw_tab,
                                              const float* __restrict__ rh_tab) {
  __shared__ float sk[8][512];
  __shared__ float sv[8][512];
  __shared__ float srel[252];
  int is_col = blockIdx.y;
  const float* rel = is_col ? rh_tab : rw_tab;
  int tid = threadIdx.x;
  for (int i = tid; i < 252; i += 256) srel[i] = rel[i];
  int w = tid >> 5, lane = tid & 31;
  int r = blockIdx.x * 8 + w;
  int fixed = r & 31;
  int bn = r >> 5;
  int n = bn & 3, bimg = bn >> 2;

  if (!is_col) {
    const float* kb = &g_k[(size_t)(bn * 32 + fixed) * 512];
    const float* vbp = &g_v[(size_t)(bn * 32 + fixed) * 512];
    for (int i = lane; i < 128; i += 32) {
      ((float4*)sk[w])[i] = ((const float4*)kb)[i];
      ((float4*)sv[w])[i] = ((const float4*)vbp)[i];
    }
  } else {
    for (int i = lane; i < 128; i += 32) {
      int j = i >> 2, d4 = i & 3;
      size_t off = (((size_t)(bn * 32 + j) * 32 + fixed) * 16) >> 2;
      ((float4*)sk[w])[i] = ((const float4*)g_k)[off + d4];
      ((float4*)sv[w])[i] = ((const float4*)g_v)[off + d4];
    }
  }
  __syncthreads();

  size_t qoff = is_col ? (((size_t)(bn * 32 + lane) * 32 + fixed) * 16)
                       : (((size_t)(bn * 32 + fixed) * 32 + lane) * 16);
  float4 q0 = *(const float4*)&g_q[qoff];
  float4 q1 = *(const float4*)&g_q[qoff + 4];
  float4 q2 = *(const float4*)&g_q[qoff + 8];
  float4 q3 = *(const float4*)&g_q[qoff + 12];

  const float* rl = &srel[n * 63 + lane + 31];
  float s[32];
  float mx = -1e30f;
#pragma unroll
  for (int j = 0; j < 32; j++) {
    float4 k0 = *(const float4*)&sk[w][j * 16];
    float4 k1 = *(const float4*)&sk[w][j * 16 + 4];
    float4 k2 = *(const float4*)&sk[w][j * 16 + 8];
    float4 k3 = *(const float4*)&sk[w][j * 16 + 12];
    float a = rl[-j];
    a += q0.x * k0.x + q0.y * k0.y + q0.z * k0.z + q0.w * k0.w;
    a += q1.x * k1.x + q1.y * k1.y + q1.z * k1.z + q1.w * k1.w;
    a += q2.x * k2.x + q2.y * k2.y + q2.z * k2.z + q2.w * k2.w;
    a += q3.x * k3.x + q3.y * k3.y + q3.z * k3.z + q3.w * k3.w;
    s[j] = a;
    mx = fmaxf(mx, a);
  }
  float sum = 0.f;
#pragma unroll
  for (int j = 0; j < 32; j++) { s[j] = __expf(s[j] - mx); sum += s[j]; }
  float inv = 1.f / sum;
  float4 o0 = make_float4(0, 0, 0, 0), o1 = o0, o2 = o0, o3 = o0;
#pragma unroll
  for (int j = 0; j < 32; j++) {
    float p = s[j];
    float4 v0 = *(const float4*)&sv[w][j * 16];
    float4 v1 = *(const float4*)&sv[w][j * 16 + 4];
    float4 v2 = *(const float4*)&sv[w][j * 16 + 8];
    float4 v3 = *(const float4*)&sv[w][j * 16 + 12];
    o0.x += p * v0.x; o0.y += p * v0.y; o0.z += p * v0.z; o0.w += p * v0.w;
    o1.x += p * v1.x; o1.y += p * v1.y; o1.z += p * v1.z; o1.w += p * v1.w;
    o2.x += p * v2.x; o2.y += p * v2.y; o2.z += p * v2.z; o2.w += p * v2.w;
    o3.x += p * v3.x; o3.y += p * v3.y; o3.z += p * v3.z; o3.w += p * v3.w;
  }
  o0.x *= inv; o0.y *= inv; o0.z *= inv; o0.w *= inv;
  o1.x *= inv; o1.y *= inv; o1.z *= inv; o1.w *= inv;
  o2.x *= inv; o2.y *= inv; o2.z *= inv; o2.w *= inv;
  o3.x *= inv; o3.y *= inv; o3.z *= inv; o3.w *= inv;
  size_t ooff = is_col ? (((size_t)(bimg * 32 + lane) * 32 + fixed) * 64 + n * 16)
                       : (((size_t)(bimg * 32 + fixed) * 32 + lane) * 64 + n * 16);
  float* dst = is_col ? g_o2 : g_o;
  *(float4*)&dst[ooff] = o0;
  *(float4*)&dst[ooff + 4] = o1;
  *(float4*)&dst[ooff + 8] = o2;
  *(float4*)&dst[ooff + 12] = o3;
}

// ---------------- projection + residual + mean pool (staged, 256 thr) --------
__global__ void zero_pooled_k() {
  int i = blockIdx.x * blockDim.x + threadIdx.x;
  if (i < 4096) g_pooled[i] = 0.f;
}

__global__ __launch_bounds__(256) void proj_pool_k(const float* __restrict__ pw) {
  __shared__ float so[128 * 64];  // 32KB o-tile for 128 pixels
  int b = blockIdx.x >> 3, chunk = blockIdx.x & 7;
  int tid = threadIdx.x;
  size_t base = ((size_t)b * 1024 + chunk * 128) * 64;
#pragma unroll
  for (int t = 0; t < 8; t++) {
    int i = tid + t * 256;
    float4 a = ((const float4*)(g_o + base))[i];
    float4 c = ((const float4*)(g_o2 + base))[i];
    ((float4*)so)[i] = make_float4(a.x + c.x, a.y + c.y, a.z + c.z, a.w + c.w);
  }
  __syncthreads();
  int c = tid & 127, ph = tid >> 7;  // 2 halves of 64 pixels each
  float wreg[64];
#pragma unroll
  for (int d = 0; d < 64; d++) wreg[d] = pw[c * 64 + d];
  float acc = 0.f;
  int p0 = ph * 64;
  for (int p = p0; p < p0 + 64; p++) {
    float t = g_f[((size_t)b * 1024 + chunk * 128 + p) * 128 + c];
    const float* sop = &so[p * 64];
#pragma unroll
    for (int d = 0; d < 64; d++) t += sop[d] * wreg[d];
    acc += t;
  }
  atomicAdd(&g_pooled[b * 128 + c], acc);
}

__global__ void fc_k(const float* __restrict__ pb, const float* __restrict__ fw,
                     const float* __restrict__ fb, float* __restrict__ out) {
  int idx = threadIdx.x;
  if (idx >= 320) return;
  int b = idx / 10, j = idx - b * 10;
  float acc = fb[j];
  for (int c = 0; c < 128; c++)
    acc += (g_pooled[b * 128 + c] * (1.f / 1024.f) + pb[c]) * fw[j * 128 + c];
  out[idx] = acc;
}

// ---------------- launch ----------------
extern "C" void kernel_launch(void* const* d_in, const int* in_sizes, int n_in,
                              void* d_out, int out_size) {
  const float* x   = (const float*)d_in[0];
  const float* c1w = (const float*)d_in[1];
  const float* c1b = (const float*)d_in[2];
  const float* c2w = (const float*)d_in[3];
  const float* c2b = (const float*)d_in[4];
  const float* qw  = (const float*)d_in[5];
  const float* qb  = (const float*)d_in[6];
  const float* kw  = (const float*)d_in[7];
  const float* kb  = (const float*)d_in[8];
  const float* vw  = (const float*)d_in[9];
  const float* vb  = (const float*)d_in[10];
  const float* pw  = (const float*)d_in[11];
  const float* pb  = (const float*)d_in[12];
  const float* rh  = (const float*)d_in[13];
  const float* rw  = (const float*)d_in[14];
  const float* fw  = (const float*)d_in[15];
  const float* fb  = (const float*)d_in[16];
  float* out = (float*)d_out;

  prep_w2_k<<<288, 256>>>(c2w);
  conv1_pool_k<<<512, 256>>>(x, c1w, c1b);
  conv2_pool_k<<<2048, 256>>>(c2b);
  qkv_k<<<dim3(256, 3), 256>>>(qw, qb, kw, kb, vw, vb);
  attn_k<<<dim3(512, 2), 256>>>(rw, rh);
  zero_pooled_k<<<4, 1024>>>();
  proj_pool_k<<<256, 256>>>(pw);
  fc_k<<<1, 320>>>(pb, fw, fb, out);
}

// round 6
// speedup vs baseline: 1.0025x; 1.0025x over previous
#include <cuda_runtime.h>

// ---------------- scratch (static device globals; no allocation) ----------------
__device__ float g_h1[8388608];   // [32][64][64][64]  conv1+pool out, NHWC
__device__ float g_f[4194304];    // [32][32][32][128] conv2+pool out, NHWC
__device__ float g_w2t[73728];    // conv2 weights transposed: [ic][woff][oc]
__device__ float g_q[2097152];    // [b*4+n][y][x][16]
__device__ float g_k[2097152];
__device__ float g_v[2097152];
__device__ float g_o[2097152];    // row-attn out [b][y][x][64]
__device__ float g_o2[2097152];   // col-attn out [b][y][x][64]
__device__ float g_pooled[4096];  // [32][128]

// ---------------- packed f32x2 helpers ----------------
__device__ __forceinline__ void ffma2(unsigned long long& d, unsigned long long a,
                                      unsigned long long b) {
  asm("fma.rn.f32x2 %0, %1, %2, %0;" : "+l"(d) : "l"(a), "l"(b));
}
__device__ __forceinline__ unsigned long long pk(float lo, float hi) {
  unsigned long long r;
  asm("mov.b64 %0, {%1,%2};" : "=l"(r) : "f"(lo), "f"(hi));
  return r;
}
__device__ __forceinline__ unsigned long long pk2(float v) { return pk(v, v); }
__device__ __forceinline__ float2 upk(unsigned long long v) {
  float2 r;
  asm("mov.b64 {%0,%1}, %2;" : "=f"(r.x), "=f"(r.y) : "l"(v));
  return r;
}

// ---------------- conv2 weight transpose prep ----------------
__global__ void prep_w2_k(const float* __restrict__ w) {
  int i = blockIdx.x * 256 + threadIdx.x;  // i = ((ic*9)+woff)*128 + oc
  if (i < 73728) {
    int oc = i & 127;
    int rest = i >> 7;
    int woff = rest % 9, ic = rest / 9;
    g_w2t[i] = w[(size_t)oc * 576 + ic * 9 + woff];
  }
}

// ---------------- conv1 (3->64) + relu + maxpool2 (FFMA2) --------------------
__global__ __launch_bounds__(256) void conv1_pool_k(const float* __restrict__ x,
                                                    const float* __restrict__ w,
                                                    const float* __restrict__ bias) {
  __shared__ unsigned long long sw2[1728];  // duplicated (w,w) pairs
  __shared__ float sb[64];
  for (int i = threadIdx.x; i < 1728; i += 256) sw2[i] = pk2(w[i]);
  if (threadIdx.x < 64) sb[threadIdx.x] = bias[threadIdx.x];
  __syncthreads();
  int idx = blockIdx.x * 256 + threadIdx.x;  // (b,py,px) pooled pixel
  int px = idx & 63, py = (idx >> 6) & 63, b = idx >> 12;

  unsigned long long inp[3][4][3];  // [c][row][kw]: (in[r][kw], in[r][kw+1])
#pragma unroll
  for (int c = 0; c < 3; c++) {
#pragma unroll
    for (int r = 0; r < 4; r++) {
      int iy = 2 * py - 1 + r;
      bool yok = (iy >= 0 && iy < 128);
      const float* xr = x + ((size_t)(b * 3 + c) * 128 + (yok ? iy : 0)) * 128;
      float rowv[4];
#pragma unroll
      for (int cc = 0; cc < 4; cc++) {
        int ix = 2 * px - 1 + cc;
        rowv[cc] = (yok && ix >= 0 && ix < 128) ? xr[ix] : 0.f;
      }
#pragma unroll
      for (int kw = 0; kw < 3; kw++) inp[c][r][kw] = pk(rowv[kw], rowv[kw + 1]);
    }
  }
  float* outp = &g_h1[(size_t)idx * 64];
  float4 vbuf;
  float* vb = (float*)&vbuf;
  for (int oc = 0; oc < 64; oc++) {
    float bsv = sb[oc];
    unsigned long long a01 = pk2(bsv);
    unsigned long long a23 = pk2(bsv);
    const unsigned long long* wp = &sw2[oc * 27];
#pragma unroll
    for (int c = 0; c < 3; c++)
#pragma unroll
      for (int kh = 0; kh < 3; kh++)
#pragma unroll
        for (int kw = 0; kw < 3; kw++) {
          unsigned long long wv = wp[c * 9 + kh * 3 + kw];
          ffma2(a01, inp[c][kh][kw], wv);
          ffma2(a23, inp[c][kh + 1][kw], wv);
        }
    float2 f01 = upk(a01), f23 = upk(a23);
    float m = fmaxf(fmaxf(f01.x, f01.y), fmaxf(f23.x, f23.y));
    vb[oc & 3] = fmaxf(m, 0.f);
    if ((oc & 3) == 3) ((float4*)outp)[oc >> 2] = vbuf;
  }
}

// ---------------- conv2 (64->128) + relu + maxpool2 (FFMA2 v2: 731-proven) ---
// block: 256 threads = 16 pixels (4x4 pooled tile) x 16 oc-groups (8 oc each)
// scalar s_in in smem (LDS.32), pairs built in registers via pk2 (ALU pipe).
__global__ __launch_bounds__(256) void conv2_pool_k(const float* __restrict__ bias) {
  __shared__ float s_in[100 * 33];  // 10x10 spatial x 32 ch, stride 33
  int b = blockIdx.x >> 6;
  int tile = blockIdx.x & 63;
  int ty0 = (tile >> 3) * 4;
  int tx0 = (tile & 7) * 4;
  int tid = threadIdx.x;
  int pix = tid & 15;
  int px = pix & 3, py = pix >> 2;
  int oc0 = (tid >> 4) * 8;

  unsigned long long acc2[4][4];  // [ocpair][pos]
#pragma unroll
  for (int pr = 0; pr < 4; pr++) {
    unsigned long long bp = pk(bias[oc0 + 2 * pr], bias[oc0 + 2 * pr + 1]);
#pragma unroll
    for (int p = 0; p < 4; p++) acc2[pr][p] = bp;
  }

  for (int ic0 = 0; ic0 < 64; ic0 += 32) {
    __syncthreads();
    for (int i = tid; i < 100 * 32; i += 256) {
      int c = i & 31;
      int rc = i >> 5;
      int row = rc / 10, col = rc - row * 10;
      int iy = 2 * ty0 - 1 + row;
      int ix = 2 * tx0 - 1 + col;
      float val = 0.f;
      if (iy >= 0 && iy < 64 && ix >= 0 && ix < 64)
        val = g_h1[((size_t)(b * 64 + iy) * 64 + ix) * 64 + ic0 + c];
      s_in[rc * 33 + c] = val;
    }
    __syncthreads();
#pragma unroll 2
    for (int ic = 0; ic < 32; ic++) {
      unsigned long long ivp[4][4];
#pragma unroll
      for (int r = 0; r < 4; r++)
#pragma unroll
        for (int cc = 0; cc < 4; cc++)
          ivp[r][cc] = pk2(s_in[((2 * py + r) * 10 + 2 * px + cc) * 33 + ic]);
      const float* wb = &g_w2t[(size_t)(ic0 + ic) * 1152 + oc0];
#pragma unroll
      for (int kh = 0; kh < 3; kh++)
#pragma unroll
        for (int kw = 0; kw < 3; kw++) {
          int woff = kh * 3 + kw;
          ulonglong2 wA = *(const ulonglong2*)(wb + woff * 128);
          ulonglong2 wB = *(const ulonglong2*)(wb + woff * 128 + 4);
#pragma unroll
          for (int p = 0; p < 4; p++) {
            unsigned long long a = ivp[kh + (p >> 1)][kw + (p & 1)];
            ffma2(acc2[0][p], a, wA.x);
            ffma2(acc2[1][p], a, wA.y);
            ffma2(acc2[2][p], a, wB.x);
            ffma2(acc2[3][p], a, wB.y);
          }
        }
    }
  }
  int y = ty0 + py, xo = tx0 + px;
  float* outp = &g_f[((size_t)(b * 32 + y) * 32 + xo) * 128 + oc0];
  float res[8];
#pragma unroll
  for (int pr = 0; pr < 4; pr++) {
    float2 f0 = upk(acc2[pr][0]), f1 = upk(acc2[pr][1]);
    float2 f2 = upk(acc2[pr][2]), f3 = upk(acc2[pr][3]);
    res[2 * pr] = fmaxf(fmaxf(fmaxf(f0.x, f1.x), fmaxf(f2.x, f3.x)), 0.f);
    res[2 * pr + 1] = fmaxf(fmaxf(fmaxf(f0.y, f1.y), fmaxf(f2.y, f3.y)), 0.f);
  }
  ((float4*)outp)[0] = make_float4(res[0], res[1], res[2], res[3]);
  ((float4*)outp)[1] = make_float4(res[4], res[5], res[6], res[7]);
}

// ---------------- fused Q/K/V projection (FFMA2 m-pairs) ---------------------
// tile M=128 (64 m-pairs) x N=64; thread: ty(0..31) -> 2 m-pairs, tx(0..7) -> 8 n
// As2 holds (f[2mp][k], f[2mp+1][k]) pairs (no duplication); Bs2 holds dup weights.
__global__ __launch_bounds__(256) void qkv_k(const float* __restrict__ qw, const float* __restrict__ qb,
                                             const float* __restrict__ kw, const float* __restrict__ kb,
                                             const float* __restrict__ vw, const float* __restrict__ vb) {
  __shared__ unsigned long long As2[64 * 33];  // [mp][kk]  16.9KB
  __shared__ unsigned long long Bs2[32 * 66];  // [kk][n]   16.9KB
  int which = blockIdx.y;
  const float* W = which == 0 ? qw : (which == 1 ? kw : vw);
  const float* bi = which == 0 ? qb : (which == 1 ? kb : vb);
  float* dst = which == 0 ? g_q : (which == 1 ? g_k : g_v);
  float scale = which == 0 ? 0.25f : 1.0f;
  int m0 = blockIdx.x * 128;
  int tid = threadIdx.x;
  int tx = tid & 7, ty = tid >> 3;
  unsigned long long acc2[2][8] = {};
  for (int k0 = 0; k0 < 128; k0 += 32) {
    __syncthreads();
#pragma unroll
    for (int t = 0; t < 2; t++) {
      int i = tid + t * 256;       // 512 float4 groups: mp = i>>3, f4 = i&7
      int mp = i >> 3, f4 = i & 7;
      const float* ra = &g_f[(size_t)(m0 + 2 * mp) * 128 + k0 + f4 * 4];
      float4 a = *(const float4*)ra;
      float4 bq = *(const float4*)(ra + 128);
      unsigned long long* d = &As2[mp * 33 + f4 * 4];
      d[0] = pk(a.x, bq.x); d[1] = pk(a.y, bq.y);
      d[2] = pk(a.z, bq.z); d[3] = pk(a.w, bq.w);
    }
#pragma unroll
    for (int t = 0; t < 8; t++) {
      int i = tid + t * 256;
      int kk = i & 31, n = i >> 5;
      Bs2[kk * 66 + n] = pk2(W[(size_t)n * 128 + k0 + kk]);
    }
    __syncthreads();
#pragma unroll
    for (int kk = 0; kk < 32; kk++) {
      unsigned long long a0 = As2[(ty * 2) * 33 + kk];
      unsigned long long a1 = As2[(ty * 2 + 1) * 33 + kk];
      const unsigned long long* wp = &Bs2[kk * 66 + tx * 8];
      ulonglong2 w01 = *(const ulonglong2*)(wp);
      ulonglong2 w23 = *(const ulonglong2*)(wp + 2);
      ulonglong2 w45 = *(const ulonglong2*)(wp + 4);
      ulonglong2 w67 = *(const ulonglong2*)(wp + 6);
      ffma2(acc2[0][0], a0, w01.x); ffma2(acc2[0][1], a0, w01.y);
      ffma2(acc2[0][2], a0, w23.x); ffma2(acc2[0][3], a0, w23.y);
      ffma2(acc2[0][4], a0, w45.x); ffma2(acc2[0][5], a0, w45.y);
      ffma2(acc2[0][6], a0, w67.x); ffma2(acc2[0][7], a0, w67.y);
      ffma2(acc2[1][0], a1, w01.x); ffma2(acc2[1][1], a1, w01.y);
      ffma2(acc2[1][2], a1, w23.x); ffma2(acc2[1][3], a1, w23.y);
      ffma2(acc2[1][4], a1, w45.x); ffma2(acc2[1][5], a1, w45.y);
      ffma2(acc2[1][6], a1, w67.x); ffma2(acc2[1][7], a1, w67.y);
    }
  }
  int head = tx >> 1, d0 = (tx & 1) * 8;
  float bv[8];
#pragma unroll
  for (int j = 0; j < 8; j++) bv[j] = bi[tx * 8 + j];
#pragma unroll
  for (int i = 0; i < 2; i++) {
    float2 p[8];
#pragma unroll
    for (int j = 0; j < 8; j++) p[j] = upk(acc2[i][j]);
#pragma unroll
    for (int par = 0; par < 2; par++) {
      int m = m0 + ty * 4 + 2 * i + par;
      int bimg = m >> 10, y = (m >> 5) & 31, xx = m & 31;
      size_t base = ((size_t)(bimg * 4 + head) * 1024 + y * 32 + xx) * 16 + d0;
      float v0 = par ? p[0].y : p[0].x, v1 = par ? p[1].y : p[1].x;
      float v2 = par ? p[2].y : p[2].x, v3 = par ? p[3].y : p[3].x;
      float v4 = par ? p[4].y : p[4].x, v5 = par ? p[5].y : p[5].x;
      float v6 = par ? p[6].y : p[6].x, v7 = par ? p[7].y : p[7].x;
      *(float4*)&dst[base] = make_float4((v0 + bv[0]) * scale, (v1 + bv[1]) * scale,
                                         (v2 + bv[2]) * scale, (v3 + bv[3]) * scale);
      *(float4*)&dst[base + 4] = make_float4((v4 + bv[4]) * scale, (v5 + bv[5]) * scale,
                                             (v6 + bv[6]) * scale, (v7 + bv[7]) * scale);
    }
  }
}

// ---------------- axial attention: merged row+col, float4 smem reads ----------
__global__ __launch_bounds__(256) void attn_k(const float* __restrict__ rw_tab,
                                              const float* __restrict__ rh_tab) {
  __shared__ float sk[8][512];
  __shared__ float sv[8][512];
  __shared__ float srel[252];
  int is_col = blockIdx.y;
  const float* rel = is_col ? rh_tab : rw_tab;
  int tid = threadIdx.x;
  for (int i = tid; i < 252; i += 256) srel[i] = rel[i];
  int w = tid >> 5, lane = tid & 31;
  int r = blockIdx.x * 8 + w;
  int fixed = r & 31;
  int bn = r >> 5;
  int n = bn & 3, bimg = bn >> 2;

  if (!is_col) {
    const float* kb = &g_k[(size_t)(bn * 32 + fixed) * 512];
    const float* vbp = &g_v[(size_t)(bn * 32 + fixed) * 512];
    for (int i = lane; i < 128; i += 32) {
      ((float4*)sk[w])[i] = ((const float4*)kb)[i];
      ((float4*)sv[w])[i] = ((const float4*)vbp)[i];
    }
  } else {
    for (int i = lane; i < 128; i += 32) {
      int j = i >> 2, d4 = i & 3;
      size_t off = (((size_t)(bn * 32 + j) * 32 + fixed) * 16) >> 2;
      ((float4*)sk[w])[i] = ((const float4*)g_k)[off + d4];
      ((float4*)sv[w])[i] = ((const float4*)g_v)[off + d4];
    }
  }
  __syncthreads();

  size_t qoff = is_col ? (((size_t)(bn * 32 + lane) * 32 + fixed) * 16)
                       : (((size_t)(bn * 32 + fixed) * 32 + lane) * 16);
  float4 q0 = *(const float4*)&g_q[qoff];
  float4 q1 = *(const float4*)&g_q[qoff + 4];
  float4 q2 = *(const float4*)&g_q[qoff + 8];
  float4 q3 = *(const float4*)&g_q[qoff + 12];

  const float* rl = &srel[n * 63 + lane + 31];
  float s[32];
  float mx = -1e30f;
#pragma unroll
  for (int j = 0; j < 32; j++) {
    float4 k0 = *(const float4*)&sk[w][j * 16];
    float4 k1 = *(const float4*)&sk[w][j * 16 + 4];
    float4 k2 = *(const float4*)&sk[w][j * 16 + 8];
    float4 k3 = *(const float4*)&sk[w][j * 16 + 12];
    float a = rl[-j];
    a += q0.x * k0.x + q0.y * k0.y + q0.z * k0.z + q0.w * k0.w;
    a += q1.x * k1.x + q1.y * k1.y + q1.z * k1.z + q1.w * k1.w;
    a += q2.x * k2.x + q2.y * k2.y + q2.z * k2.z + q2.w * k2.w;
    a += q3.x * k3.x + q3.y * k3.y + q3.z * k3.z + q3.w * k3.w;
    s[j] = a;
    mx = fmaxf(mx, a);
  }
  float sum = 0.f;
#pragma unroll
  for (int j = 0; j < 32; j++) { s[j] = __expf(s[j] - mx); sum += s[j]; }
  float inv = 1.f / sum;
  float4 o0 = make_float4(0, 0, 0, 0), o1 = o0, o2 = o0, o3 = o0;
#pragma unroll
  for (int j = 0; j < 32; j++) {
    float p = s[j];
    float4 v0 = *(const float4*)&sv[w][j * 16];
    float4 v1 = *(const float4*)&sv[w][j * 16 + 4];
    float4 v2 = *(const float4*)&sv[w][j * 16 + 8];
    float4 v3 = *(const float4*)&sv[w][j * 16 + 12];
    o0.x += p * v0.x; o0.y += p * v0.y; o0.z += p * v0.z; o0.w += p * v0.w;
    o1.x += p * v1.x; o1.y += p * v1.y; o1.z += p * v1.z; o1.w += p * v1.w;
    o2.x += p * v2.x; o2.y += p * v2.y; o2.z += p * v2.z; o2.w += p * v2.w;
    o3.x += p * v3.x; o3.y += p * v3.y; o3.z += p * v3.z; o3.w += p * v3.w;
  }
  o0.x *= inv; o0.y *= inv; o0.z *= inv; o0.w *= inv;
  o1.x *= inv; o1.y *= inv; o1.z *= inv; o1.w *= inv;
  o2.x *= inv; o2.y *= inv; o2.z *= inv; o2.w *= inv;
  o3.x *= inv; o3.y *= inv; o3.z *= inv; o3.w *= inv;
  size_t ooff = is_col ? (((size_t)(bimg * 32 + lane) * 32 + fixed) * 64 + n * 16)
                       : (((size_t)(bimg * 32 + fixed) * 32 + lane) * 64 + n * 16);
  float* dst = is_col ? g_o2 : g_o;
  *(float4*)&dst[ooff] = o0;
  *(float4*)&dst[ooff + 4] = o1;
  *(float4*)&dst[ooff + 8] = o2;
  *(float4*)&dst[ooff + 12] = o3;
}

// ---------------- projection + residual + mean pool (staged, 256 thr) --------
__global__ void zero_pooled_k() {
  int i = blockIdx.x * blockDim.x + threadIdx.x;
  if (i < 4096) g_pooled[i] = 0.f;
}

__global__ __launch_bounds__(256) void proj_pool_k(const float* __restrict__ pw) {
  __shared__ float so[128 * 64];  // 32KB o-tile for 128 pixels
  int b = blockIdx.x >> 3, chunk = blockIdx.x & 7;
  int tid = threadIdx.x;
  size_t base = ((size_t)b * 1024 + chunk * 128) * 64;
#pragma unroll
  for (int t = 0; t < 8; t++) {
    int i = tid + t * 256;
    float4 a = ((const float4*)(g_o + base))[i];
    float4 c = ((const float4*)(g_o2 + base))[i];
    ((float4*)so)[i] = make_float4(a.x + c.x, a.y + c.y, a.z + c.z, a.w + c.w);
  }
  __syncthreads();
  int c = tid & 127, ph = tid >> 7;  // 2 halves of 64 pixels each
  float wreg[64];
#pragma unroll
  for (int d = 0; d < 64; d++) wreg[d] = pw[c * 64 + d];
  float acc = 0.f;
  int p0 = ph * 64;
  for (int p = p0; p < p0 + 64; p++) {
    float t = g_f[((size_t)b * 1024 + chunk * 128 + p) * 128 + c];
    const float* sop = &so[p * 64];
#pragma unroll
    for (int d = 0; d < 64; d++) t += sop[d] * wreg[d];
    acc += t;
  }
  atomicAdd(&g_pooled[b * 128 + c], acc);
}

__global__ void fc_k(const float* __restrict__ pb, const float* __restrict__ fw,
                     const float* __restrict__ fb, float* __restrict__ out) {
  int idx = threadIdx.x;
  if (idx >= 320) return;
  int b = idx / 10, j = idx - b * 10;
  float acc = fb[j];
  for (int c = 0; c < 128; c++)
    acc += (g_pooled[b * 128 + c] * (1.f / 1024.f) + pb[c]) * fw[j * 128 + c];
  out[idx] = acc;
}

// ---------------- launch ----------------
extern "C" void kernel_launch(void* const* d_in, const int* in_sizes, int n_in,
                              void* d_out, int out_size) {
  const float* x   = (const float*)d_in[0];
  const float* c1w = (const float*)d_in[1];
  const float* c1b = (const float*)d_in[2];
  const float* c2w = (const float*)d_in[3];
  const float* c2b = (const float*)d_in[4];
  const float* qw  = (const float*)d_in[5];
  const float* qb  = (const float*)d_in[6];
  const float* kw  = (const float*)d_in[7];
  const float* kb  = (const float*)d_in[8];
  const float* vw  = (const float*)d_in[9];
  const float* vb  = (const float*)d_in[10];
  const float* pw  = (const float*)d_in[11];
  const float* pb  = (const float*)d_in[12];
  const float* rh  = (const float*)d_in[13];
  const float* rw  = (const float*)d_in[14];
  const float* fw  = (const float*)d_in[15];
  const float* fb  = (const float*)d_in[16];
  float* out = (float*)d_out;

  prep_w2_k<<<288, 256>>>(c2w);
  conv1_pool_k<<<512, 256>>>(x, c1w, c1b);
  conv2_pool_k<<<2048, 256>>>(c2b);
  qkv_k<<<dim3(256, 3), 256>>>(qw, qb, kw, kb, vw, vb);
  attn_k<<<dim3(512, 2), 256>>>(rw, rh);
  zero_pooled_k<<<4, 1024>>>();
  proj_pool_k<<<256, 256>>>(pw);
  fc_k<<<1, 320>>>(pb, fw, fb, out);
}

// round 7
// speedup vs baseline: 1.2637x; 1.2605x over previous
#include <cuda_runtime.h>

// ---------------- scratch (static device globals; no allocation) ----------------
__device__ float g_h1[8388608];   // [32][64][64][64]  conv1+pool out, NHWC
__device__ float g_f[4194304];    // [32][32][32][128] conv2+pool out, NHWC
__device__ float g_w2t[73728];    // conv2 weights transposed: [ic][woff][oc]
__device__ float g_q[2097152];    // [b*4+n][y][x][16]
__device__ float g_k[2097152];
__device__ float g_v[2097152];
__device__ float g_o[2097152];    // row-attn out [b][y][x][64]
__device__ float g_o2[2097152];   // col-attn out [b][y][x][64]
__device__ float g_pooled[4096];  // [32][128]

// ---------------- packed f32x2 helpers ----------------
__device__ __forceinline__ void ffma2(unsigned long long& d, unsigned long long a,
                                      unsigned long long b) {
  asm("fma.rn.f32x2 %0, %1, %2, %0;" : "+l"(d) : "l"(a), "l"(b));
}
__device__ __forceinline__ unsigned long long pk(float lo, float hi) {
  unsigned long long r;
  asm("mov.b64 %0, {%1,%2};" : "=l"(r) : "f"(lo), "f"(hi));
  return r;
}
__device__ __forceinline__ unsigned long long pk2(float v) { return pk(v, v); }
__device__ __forceinline__ float2 upk(unsigned long long v) {
  float2 r;
  asm("mov.b64 {%0,%1}, %2;" : "=f"(r.x), "=f"(r.y) : "l"(v));
  return r;
}

// ---------------- conv2 weight transpose prep ----------------
__global__ void prep_w2_k(const float* __restrict__ w) {
  int i = blockIdx.x * 256 + threadIdx.x;  // i = ((ic*9)+woff)*128 + oc
  if (i < 73728) {
    int oc = i & 127;
    int rest = i >> 7;
    int woff = rest % 9, ic = rest / 9;
    g_w2t[i] = w[(size_t)oc * 576 + ic * 9 + woff];
  }
}

// ---------------- conv1 (3->64) + relu + maxpool2 (FFMA2) --------------------
__global__ __launch_bounds__(256) void conv1_pool_k(const float* __restrict__ x,
                                                    const float* __restrict__ w,
                                                    const float* __restrict__ bias) {
  __shared__ unsigned long long sw2[1728];  // duplicated (w,w) pairs
  __shared__ float sb[64];
  for (int i = threadIdx.x; i < 1728; i += 256) sw2[i] = pk2(w[i]);
  if (threadIdx.x < 64) sb[threadIdx.x] = bias[threadIdx.x];
  __syncthreads();
  int idx = blockIdx.x * 256 + threadIdx.x;  // (b,py,px) pooled pixel
  int px = idx & 63, py = (idx >> 6) & 63, b = idx >> 12;

  unsigned long long inp[3][4][3];  // [c][row][kw]: (in[r][kw], in[r][kw+1])
#pragma unroll
  for (int c = 0; c < 3; c++) {
#pragma unroll
    for (int r = 0; r < 4; r++) {
      int iy = 2 * py - 1 + r;
      bool yok = (iy >= 0 && iy < 128);
      const float* xr = x + ((size_t)(b * 3 + c) * 128 + (yok ? iy : 0)) * 128;
      float rowv[4];
#pragma unroll
      for (int cc = 0; cc < 4; cc++) {
        int ix = 2 * px - 1 + cc;
        rowv[cc] = (yok && ix >= 0 && ix < 128) ? xr[ix] : 0.f;
      }
#pragma unroll
      for (int kw = 0; kw < 3; kw++) inp[c][r][kw] = pk(rowv[kw], rowv[kw + 1]);
    }
  }
  float* outp = &g_h1[(size_t)idx * 64];
  float4 vbuf;
  float* vb = (float*)&vbuf;
  for (int oc = 0; oc < 64; oc++) {
    float bsv = sb[oc];
    unsigned long long a01 = pk2(bsv);
    unsigned long long a23 = pk2(bsv);
    const unsigned long long* wp = &sw2[oc * 27];
#pragma unroll
    for (int c = 0; c < 3; c++)
#pragma unroll
      for (int kh = 0; kh < 3; kh++)
#pragma unroll
        for (int kw = 0; kw < 3; kw++) {
          unsigned long long wv = wp[c * 9 + kh * 3 + kw];
          ffma2(a01, inp[c][kh][kw], wv);
          ffma2(a23, inp[c][kh + 1][kw], wv);
        }
    float2 f01 = upk(a01), f23 = upk(a23);
    float m = fmaxf(fmaxf(f01.x, f01.y), fmaxf(f23.x, f23.y));
    vb[oc & 3] = fmaxf(m, 0.f);
    if ((oc & 3) == 3) ((float4*)outp)[oc >> 2] = vbuf;
  }
}

// ---------------- conv2 (64->128) + relu + maxpool2 (FFMA2 v4) ---------------
// block: 256 threads = 16 slots (4x4, each slot = 2 adjacent pooled px) x 16 oc-grp
// 288 FFMA2 per ic per thread over the same 18 weight LDGs (2x latency runway).
__global__ __launch_bounds__(256) void conv2_pool_k(const float* __restrict__ bias) {
  __shared__ float s_in[180 * 33];  // 10 rows x 18 cols x 32 ch, stride 33
  int b = blockIdx.x >> 5;
  int tile = blockIdx.x & 31;
  int ty0 = (tile >> 2) * 4;   // pooled tile origin: 8 wide x 4 tall
  int tx0 = (tile & 3) * 8;
  int tid = threadIdx.x;
  int slot = tid & 15;
  int px2 = slot & 3, py = slot >> 2;  // slot covers pooled px tx0+2*px2 +{0,1}
  int oc0 = (tid >> 4) * 8;

  unsigned long long acc2[4][8];  // [ocpair][pos]; pos = r*4 + c (conv coords)
#pragma unroll
  for (int pr = 0; pr < 4; pr++) {
    unsigned long long bp = pk(bias[oc0 + 2 * pr], bias[oc0 + 2 * pr + 1]);
#pragma unroll
    for (int p = 0; p < 8; p++) acc2[pr][p] = bp;
  }

  for (int ic0 = 0; ic0 < 64; ic0 += 32) {
    __syncthreads();
    for (int i = tid; i < 180 * 32; i += 256) {
      int c = i & 31;
      int rc = i >> 5;
      int row = rc / 18, col = rc - row * 18;
      int iy = 2 * ty0 - 1 + row;
      int ix = 2 * tx0 - 1 + col;
      float val = 0.f;
      if (iy >= 0 && iy < 64 && ix >= 0 && ix < 64)
        val = g_h1[((size_t)(b * 64 + iy) * 64 + ix) * 64 + ic0 + c];
      s_in[rc * 33 + c] = val;
    }
    __syncthreads();
#pragma unroll 2
    for (int ic = 0; ic < 32; ic++) {
      unsigned long long ivp[4][6];  // rows 2py+0..3, cols 4px2+0..5 (duplicated)
#pragma unroll
      for (int r = 0; r < 4; r++)
#pragma unroll
        for (int cc = 0; cc < 6; cc++)
          ivp[r][cc] = pk2(s_in[((2 * py + r) * 18 + 4 * px2 + cc) * 33 + ic]);
      const float* wb = &g_w2t[(size_t)(ic0 + ic) * 1152 + oc0];
#pragma unroll
      for (int kh = 0; kh < 3; kh++)
#pragma unroll
        for (int kw = 0; kw < 3; kw++) {
          int woff = kh * 3 + kw;
          ulonglong2 wA = *(const ulonglong2*)(wb + woff * 128);
          ulonglong2 wB = *(const ulonglong2*)(wb + woff * 128 + 4);
#pragma unroll
          for (int p = 0; p < 8; p++) {
            unsigned long long a = ivp[kh + (p >> 2)][kw + (p & 3)];
            ffma2(acc2[0][p], a, wA.x);
            ffma2(acc2[1][p], a, wA.y);
            ffma2(acc2[2][p], a, wB.x);
            ffma2(acc2[3][p], a, wB.y);
          }
        }
    }
  }
  int y = ty0 + py;
#pragma unroll
  for (int w = 0; w < 2; w++) {  // two pooled pixels: conv cols {2w, 2w+1}
    int xo = tx0 + 2 * px2 + w;
    float* outp = &g_f[((size_t)(b * 32 + y) * 32 + xo) * 128 + oc0];
    float res[8];
#pragma unroll
    for (int pr = 0; pr < 4; pr++) {
      float2 f0 = upk(acc2[pr][0 + 2 * w]), f1 = upk(acc2[pr][1 + 2 * w]);
      float2 f2 = upk(acc2[pr][4 + 2 * w]), f3 = upk(acc2[pr][5 + 2 * w]);
      res[2 * pr] = fmaxf(fmaxf(fmaxf(f0.x, f1.x), fmaxf(f2.x, f3.x)), 0.f);
      res[2 * pr + 1] = fmaxf(fmaxf(fmaxf(f0.y, f1.y), fmaxf(f2.y, f3.y)), 0.f);
    }
    ((float4*)outp)[0] = make_float4(res[0], res[1], res[2], res[3]);
    ((float4*)outp)[1] = make_float4(res[4], res[5], res[6], res[7]);
  }
}

// ---------------- fused Q/K/V projection (8x8 register tiling, round-3 exact) -
__global__ __launch_bounds__(256) void qkv_k(const float* __restrict__ qw, const float* __restrict__ qb,
                                             const float* __restrict__ kw, const float* __restrict__ kb,
                                             const float* __restrict__ vw, const float* __restrict__ vb) {
  __shared__ float As[256 * 33];  // [m][kk]
  __shared__ float Bs[32 * 68];   // [kk][n] (k-major, float4-readable)
  int which = blockIdx.y;
  const float* W = which == 0 ? qw : (which == 1 ? kw : vw);
  const float* bi = which == 0 ? qb : (which == 1 ? kb : vb);
  float* dst = which == 0 ? g_q : (which == 1 ? g_k : g_v);
  float scale = which == 0 ? 0.25f : 1.0f;
  int m0 = blockIdx.x * 256;
  int tid = threadIdx.x;
  int tx = tid & 7, ty = tid >> 3;
  float acc[8][8] = {};
  for (int k0 = 0; k0 < 128; k0 += 32) {
    __syncthreads();
#pragma unroll
    for (int t = 0; t < 32; t++) {
      int i = tid + t * 256;
      int kk = i & 31, r = i >> 5;
      As[r * 33 + kk] = g_f[(size_t)(m0 + r) * 128 + k0 + kk];
    }
#pragma unroll
    for (int t = 0; t < 8; t++) {
      int i = tid + t * 256;
      int kk = i & 31, n = i >> 5;
      Bs[kk * 68 + n] = W[(size_t)n * 128 + k0 + kk];
    }
    __syncthreads();
#pragma unroll
    for (int kk = 0; kk < 32; kk++) {
      float4 b0 = *(const float4*)&Bs[kk * 68 + tx * 8];
      float4 b1 = *(const float4*)&Bs[kk * 68 + tx * 8 + 4];
      float bv[8] = {b0.x, b0.y, b0.z, b0.w, b1.x, b1.y, b1.z, b1.w};
      float a[8];
#pragma unroll
      for (int i = 0; i < 8; i++) a[i] = As[(ty * 8 + i) * 33 + kk];
#pragma unroll
      for (int i = 0; i < 8; i++)
#pragma unroll
        for (int j = 0; j < 8; j++) acc[i][j] += a[i] * bv[j];
    }
  }
  int n = tx >> 1, d0 = (tx & 1) * 8;
#pragma unroll
  for (int i = 0; i < 8; i++) {
    int m = m0 + ty * 8 + i;
    int bimg = m >> 10, y = (m >> 5) & 31, xx = m & 31;
    size_t base = ((size_t)(bimg * 4 + n) * 1024 + y * 32 + xx) * 16 + d0;
    float4 o0 = make_float4((acc[i][0] + bi[tx * 8 + 0]) * scale,
                            (acc[i][1] + bi[tx * 8 + 1]) * scale,
                            (acc[i][2] + bi[tx * 8 + 2]) * scale,
                            (acc[i][3] + bi[tx * 8 + 3]) * scale);
    float4 o1 = make_float4((acc[i][4] + bi[tx * 8 + 4]) * scale,
                            (acc[i][5] + bi[tx * 8 + 5]) * scale,
                            (acc[i][6] + bi[tx * 8 + 6]) * scale,
                            (acc[i][7] + bi[tx * 8 + 7]) * scale);
    *(float4*)&dst[base] = o0;
    *(float4*)&dst[base + 4] = o1;
  }
}

// ---------------- axial attention: merged row+col, float4 smem reads ----------
__global__ __launch_bounds__(256) void attn_k(const float* __restrict__ rw_tab,
                                              const float* __restrict__ rh_tab) {
  __shared__ float sk[8][512];
  __shared__ float sv[8][512];
  __shared__ float srel[252];
  int is_col = blockIdx.y;
  const float* rel = is_col ? rh_tab : rw_tab;
  int tid = threadIdx.x;
  for (int i = tid; i < 252; i += 256) srel[i] = rel[i];
  int w = tid >> 5, lane = tid & 31;
  int r = blockIdx.x * 8 + w;
  int fixed = r & 31;
  int bn = r >> 5;
  int n = bn & 3, bimg = bn >> 2;

  if (!is_col) {
    const float* kb = &g_k[(size_t)(bn * 32 + fixed) * 512];
    const float* vbp = &g_v[(size_t)(bn * 32 + fixed) * 512];
    for (int i = lane; i < 128; i += 32) {
      ((float4*)sk[w])[i] = ((const float4*)kb)[i];
      ((float4*)sv[w])[i] = ((const float4*)vbp)[i];
    }
  } else {
    for (int i = lane; i < 128; i += 32) {
      int j = i >> 2, d4 = i & 3;
      size_t off = (((size_t)(bn * 32 + j) * 32 + fixed) * 16) >> 2;
      ((float4*)sk[w])[i] = ((const float4*)g_k)[off + d4];
      ((float4*)sv[w])[i] = ((const float4*)g_v)[off + d4];
    }
  }
  __syncthreads();

  size_t qoff = is_col ? (((size_t)(bn * 32 + lane) * 32 + fixed) * 16)
                       : (((size_t)(bn * 32 + fixed) * 32 + lane) * 16);
  float4 q0 = *(const float4*)&g_q[qoff];
  float4 q1 = *(const float4*)&g_q[qoff + 4];
  float4 q2 = *(const float4*)&g_q[qoff + 8];
  float4 q3 = *(const float4*)&g_q[qoff + 12];

  const float* rl = &srel[n * 63 + lane + 31];
  float s[32];
  float mx = -1e30f;
#pragma unroll
  for (int j = 0; j < 32; j++) {
    float4 k0 = *(const float4*)&sk[w][j * 16];
    float4 k1 = *(const float4*)&sk[w][j * 16 + 4];
    float4 k2 = *(const float4*)&sk[w][j * 16 + 8];
    float4 k3 = *(const float4*)&sk[w][j * 16 + 12];
    float a = rl[-j];
    a += q0.x * k0.x + q0.y * k0.y + q0.z * k0.z + q0.w * k0.w;
    a += q1.x * k1.x + q1.y * k1.y + q1.z * k1.z + q1.w * k1.w;
    a += q2.x * k2.x + q2.y * k2.y + q2.z * k2.z + q2.w * k2.w;
    a += q3.x * k3.x + q3.y * k3.y + q3.z * k3.z + q3.w * k3.w;
    s[j] = a;
    mx = fmaxf(mx, a);
  }
  float sum = 0.f;
#pragma unroll
  for (int j = 0; j < 32; j++) { s[j] = __expf(s[j] - mx); sum += s[j]; }
  float inv = 1.f / sum;
  float4 o0 = make_float4(0, 0, 0, 0), o1 = o0, o2 = o0, o3 = o0;
#pragma unroll
  for (int j = 0; j < 32; j++) {
    float p = s[j];
    float4 v0 = *(const float4*)&sv[w][j * 16];
    float4 v1 = *(const float4*)&sv[w][j * 16 + 4];
    float4 v2 = *(const float4*)&sv[w][j * 16 + 8];
    float4 v3 = *(const float4*)&sv[w][j * 16 + 12];
    o0.x += p * v0.x; o0.y += p * v0.y; o0.z += p * v0.z; o0.w += p * v0.w;
    o1.x += p * v1.x; o1.y += p * v1.y; o1.z += p * v1.z; o1.w += p * v1.w;
    o2.x += p * v2.x; o2.y += p * v2.y; o2.z += p * v2.z; o2.w += p * v2.w;
    o3.x += p * v3.x; o3.y += p * v3.y; o3.z += p * v3.z; o3.w += p * v3.w;
  }
  o0.x *= inv; o0.y *= inv; o0.z *= inv; o0.w *= inv;
  o1.x *= inv; o1.y *= inv; o1.z *= inv; o1.w *= inv;
  o2.x *= inv; o2.y *= inv; o2.z *= inv; o2.w *= inv;
  o3.x *= inv; o3.y *= inv; o3.z *= inv; o3.w *= inv;
  size_t ooff = is_col ? (((size_t)(bimg * 32 + lane) * 32 + fixed) * 64 + n * 16)
                       : (((size_t)(bimg * 32 + fixed) * 32 + lane) * 64 + n * 16);
  float* dst = is_col ? g_o2 : g_o;
  *(float4*)&dst[ooff] = o0;
  *(float4*)&dst[ooff + 4] = o1;
  *(float4*)&dst[ooff + 8] = o2;
  *(float4*)&dst[ooff + 12] = o3;
}

// ---------------- projection + residual + mean pool (staged, 256 thr) --------
__global__ void zero_pooled_k() {
  int i = blockIdx.x * blockDim.x + threadIdx.x;
  if (i < 4096) g_pooled[i] = 0.f;
}

__global__ __launch_bounds__(256) void proj_pool_k(const float* __restrict__ pw) {
  __shared__ float so[128 * 64];  // 32KB o-tile for 128 pixels
  int b = blockIdx.x >> 3, chunk = blockIdx.x & 7;
  int tid = threadIdx.x;
  size_t base = ((size_t)b * 1024 + chunk * 128) * 64;
#pragma unroll
  for (int t = 0; t < 8; t++) {
    int i = tid + t * 256;
    float4 a = ((const float4*)(g_o + base))[i];
    float4 c = ((const float4*)(g_o2 + base))[i];
    ((float4*)so)[i] = make_float4(a.x + c.x, a.y + c.y, a.z + c.z, a.w + c.w);
  }
  __syncthreads();
  int c = tid & 127, ph = tid >> 7;  // 2 halves of 64 pixels each
  float wreg[64];
#pragma unroll
  for (int d = 0; d < 64; d++) wreg[d] = pw[c * 64 + d];
  float acc = 0.f;
  int p0 = ph * 64;
  for (int p = p0; p < p0 + 64; p++) {
    float t = g_f[((size_t)b * 1024 + chunk * 128 + p) * 128 + c];
    const float* sop = &so[p * 64];
#pragma unroll
    for (int d = 0; d < 64; d++) t += sop[d] * wreg[d];
    acc += t;
  }
  atomicAdd(&g_pooled[b * 128 + c], acc);
}

__global__ void fc_k(const float* __restrict__ pb, const float* __restrict__ fw,
                     const float* __restrict__ fb, float* __restrict__ out) {
  int idx = threadIdx.x;
  if (idx >= 320) return;
  int b = idx / 10, j = idx - b * 10;
  float acc = fb[j];
  for (int c = 0; c < 128; c++)
    acc += (g_pooled[b * 128 + c] * (1.f / 1024.f) + pb[c]) * fw[j * 128 + c];
  out[idx] = acc;
}

// ---------------- launch ----------------
extern "C" void kernel_launch(void* const* d_in, const int* in_sizes, int n_in,
                              void* d_out, int out_size) {
  const float* x   = (const float*)d_in[0];
  const float* c1w = (const float*)d_in[1];
  const float* c1b = (const float*)d_in[2];
  const float* c2w = (const float*)d_in[3];
  const float* c2b = (const float*)d_in[4];
  const float* qw  = (const float*)d_in[5];
  const float* qb  = (const float*)d_in[6];
  const float* kw  = (const float*)d_in[7];
  const float* kb  = (const float*)d_in[8];
  const float* vw  = (const float*)d_in[9];
  const float* vb  = (const float*)d_in[10];
  const float* pw  = (const float*)d_in[11];
  const float* pb  = (const float*)d_in[12];
  const float* rh  = (const float*)d_in[13];
  const float* rw  = (const float*)d_in[14];
  const float* fw  = (const float*)d_in[15];
  const float* fb  = (const float*)d_in[16];
  float* out = (float*)d_out;

  prep_w2_k<<<288, 256>>>(c2w);
  conv1_pool_k<<<512, 256>>>(x, c1w, c1b);
  conv2_pool_k<<<1024, 256>>>(c2b);
  qkv_k<<<dim3(128, 3), 256>>>(qw, qb, kw, kb, vw, vb);
  attn_k<<<dim3(512, 2), 256>>>(rw, rh);
  zero_pooled_k<<<4, 1024>>>();
  proj_pool_k<<<256, 256>>>(pw);
  fc_k<<<1, 320>>>(pb, fw, fb, out);
}